// round 9
// baseline (speedup 1.0000x reference)
#include <cuda_runtime.h>
#include <cstdint>

// B=256, N=256. Greedy masked argmax (exact reference semantics: max value,
// tie -> smallest flat index). Keys = fp32 bits; softmax values in (0,1) =>
// positive, < 1.0f => order-monotone uint32, < 2^30.
// Packed slot: u64 h = (key << 16) | (~((row<<8)|col) & 0xFFFF); u64 max ==
// lexicographic (max key, min flat index). 0 = dead.
//
// One CTA per batch, 256 threads:
//   init: all 8 warps build per-row exact sorted TOP-8 (head -> s_top,
//         7 backups -> s_cand smem list) via per-lane sorting network +
//         8 iterative REDUX extractions.  (parallel, warms L1)
//   loop: warp 7 (highest wid => arbiter priority) runs the serial greedy
//         loop; masked heads are refilled by popping the smem candidate
//         list (exact, ~LDS cost); global rescans only on list exhaustion.
//   warps 0-6: overlapped streaming zero-fill of the output.
//   epilogue: thread tid writes row tid's single 1.0.

#define NN 256
#define FULL 0xFFFFFFFFu
typedef unsigned long long u64;

__device__ __forceinline__ u64 pairmax(u64 a, u64 b) { return a > b ? a : b; }

__device__ __forceinline__ u64 pack16(unsigned key, int row, unsigned col) {
    return ((u64)key << 16) | (u64)((~(unsigned)((row << 8) | col)) & 0xFFFFu);
}

#define CSWAP(x, y) { u64 _a = a[x], _b = a[y]; a[x] = pairmax(_a, _b); \
                      a[y] = (_a > _b) ? _b : _a; }

__global__ __launch_bounds__(256)
void greedy_perm_kernel(const float* __restrict__ scores, float* __restrict__ out) {
    __shared__ u64 s_top[NN];        // per-row head
    __shared__ u64 s_cand[NN * 7];   // per-row backups, sorted desc
    __shared__ unsigned char s_idx[NN];
    __shared__ int s_perm[NN];

    const int b    = blockIdx.x;
    const int tid  = threadIdx.x;
    const int warp = tid >> 5;
    const int lane = tid & 31;
    const float* base  = scores + (size_t)b * NN * NN;
    float*       obase = out    + (size_t)b * NN * NN;

    // ---------- parallel init: warp w -> rows w*32..w*32+31, exact top-8 ----------
    {
        const int c0 = 4 * lane;
        // depth-1 software pipeline on the row loads
        const float4* rp0 = (const float4*)(base + (size_t)(warp * 32) * NN);
        float4 A = __ldg(rp0 + lane), Bq = __ldg(rp0 + 32 + lane);
        #pragma unroll 1
        for (int rr = 0; rr < 32; rr++) {
            const int row = warp * 32 + rr;
            float4 An, Bn;
            if (rr < 31) {
                const float4* rp = (const float4*)(base + (size_t)(row + 1) * NN);
                An = __ldg(rp + lane); Bn = __ldg(rp + 32 + lane);
            }
            // pack lane's 8 values: (key<<32) | ~col  (u64 desc == key desc, col asc)
            u64 a[8];
            a[0] = ((u64)__float_as_uint(A.x)  << 32) | (unsigned)~(c0 + 0);
            a[1] = ((u64)__float_as_uint(A.y)  << 32) | (unsigned)~(c0 + 1);
            a[2] = ((u64)__float_as_uint(A.z)  << 32) | (unsigned)~(c0 + 2);
            a[3] = ((u64)__float_as_uint(A.w)  << 32) | (unsigned)~(c0 + 3);
            a[4] = ((u64)__float_as_uint(Bq.x) << 32) | (unsigned)~(128 + c0 + 0);
            a[5] = ((u64)__float_as_uint(Bq.y) << 32) | (unsigned)~(128 + c0 + 1);
            a[6] = ((u64)__float_as_uint(Bq.z) << 32) | (unsigned)~(128 + c0 + 2);
            a[7] = ((u64)__float_as_uint(Bq.w) << 32) | (unsigned)~(128 + c0 + 3);
            // 19-comparator sorting network, descending (a[0] = max)
            CSWAP(0,1) CSWAP(2,3) CSWAP(4,5) CSWAP(6,7)
            CSWAP(0,2) CSWAP(1,3) CSWAP(4,6) CSWAP(5,7)
            CSWAP(1,2) CSWAP(5,6)
            CSWAP(0,4) CSWAP(1,5) CSWAP(2,6) CSWAP(3,7)
            CSWAP(2,4) CSWAP(3,5)
            CSWAP(1,2) CSWAP(3,4) CSWAP(5,6)
            // 8 iterative extractions: warp-wide (max key, min col)
            #pragma unroll
            for (int e = 0; e < 8; e++) {
                const unsigned k1 = (unsigned)(a[0] >> 32);
                const unsigned c1 = (~(unsigned)a[0]) & 255u;
                const unsigned m  = __reduce_max_sync(FULL, k1);
                const unsigned p  = __reduce_min_sync(FULL, (k1 == m) ? c1 : FULL);
                if (k1 == m && c1 == p) {   // winner lane: shift list down
                    #pragma unroll
                    for (int i = 0; i < 7; i++) a[i] = a[i + 1];
                    a[7] = 0ull;
                }
                if (lane == 0) {
                    if (e == 0) s_top[row] = pack16(m, row, p);
                    else        s_cand[row * 7 + (e - 1)] = pack16(m, row, p);
                }
            }
            if (lane == 0) s_idx[row] = 0;
            A = An; Bq = Bn;
        }
    }
    __syncthreads();

    if (warp == 7) {
        // ---------- serial greedy loop ----------
        u64 h[8];
        unsigned cmask[8];
        #pragma unroll
        for (int k = 0; k < 8; k++) cmask[k] = 0u;
        #pragma unroll
        for (int j = 0; j < 8; j++) h[j] = s_top[j * 32 + lane];

        #pragma unroll 1
        for (int it = 0; it < NN; it++) {
            u64 loc = pairmax(pairmax(pairmax(h[0], h[1]), pairmax(h[2], h[3])),
                              pairmax(pairmax(h[4], h[5]), pairmax(h[6], h[7])));
            const unsigned bk = (unsigned)(loc >> 16);
            const unsigned cp = (~(unsigned)loc) & 0xFFFFu;

            const unsigned m   = __reduce_max_sync(FULL, bk);
            const unsigned sel = __reduce_min_sync(FULL, (bk == m) ? cp : FULL);
            const int r = (int)(sel >> 8);
            const int c = (int)(sel & 255u);

            if (lane == 0) s_perm[r] = c;

            // mask col c (replicated, static indexing)
            {
                const int w2 = c >> 5; const unsigned bit = 1u << (c & 31);
                #pragma unroll
                for (int k = 0; k < 8; k++) if (k == w2) cmask[k] |= bit;
            }
            // kill assigned row
            if (lane == (r & 31)) {
                const int slot = r >> 5;
                #pragma unroll
                for (int j = 0; j < 8; j++) if (j == slot) h[j] = 0ull;
            }

            if (it == NN - 1) break;

            // heads hit by col c: pop next unmasked candidate from smem list
            unsigned need = 0u;
            #pragma unroll
            for (int j = 0; j < 8; j++) {
                if ((unsigned)(h[j] >> 16) != 0u &&
                    (((~(unsigned)h[j]) & 255u) == (unsigned)c)) {
                    const int row = j * 32 + lane;
                    int idx = (int)s_idx[row];
                    u64 nh = 0ull;
                    while (idx < 7) {
                        const u64 cand = s_cand[row * 7 + idx];
                        idx++;
                        const unsigned cc = (~(unsigned)cand) & 255u;
                        unsigned mw = 0u;
                        #pragma unroll
                        for (int k = 0; k < 8; k++)
                            if ((int)(cc >> 5) == k) mw = cmask[k];
                        if (((mw >> (cc & 31)) & 1u) == 0u) { nh = cand; break; }
                    }
                    s_idx[row] = (unsigned char)idx;
                    if (nh != 0ull) h[j] = nh;
                    else            need |= (1u << j);
                }
            }

            // rare: list exhausted -> cooperative global rescan (top-1)
            unsigned ln = __ballot_sync(FULL, need != 0u);
            while (ln) {
                const int src = __ffs(ln) - 1; ln &= ln - 1;
                unsigned em = __shfl_sync(FULL, need, src);
                while (em) {
                    const int jd = __ffs(em) - 1; em &= em - 1;
                    const int row = jd * 32 + src;
                    const float* rp = base + (size_t)row * NN;
                    u64 w[8];
                    #pragma unroll
                    for (int k = 0; k < 8; k++) {
                        const float v = __ldg(rp + k * 32 + lane);
                        const unsigned key =
                            ((cmask[k] >> lane) & 1u) ? 0u : __float_as_uint(v);
                        w[k] = ((u64)key << 32) | (unsigned)~(unsigned)(k * 32 + lane);
                    }
                    u64 lq = pairmax(pairmax(pairmax(w[0], w[1]), pairmax(w[2], w[3])),
                                     pairmax(pairmax(w[4], w[5]), pairmax(w[6], w[7])));
                    const unsigned kk = (unsigned)(lq >> 32);
                    const unsigned cc = (~(unsigned)lq) & 255u;
                    const unsigned mm = __reduce_max_sync(FULL, kk);
                    const unsigned pc = __reduce_min_sync(FULL, (kk == mm) ? cc : FULL);
                    if (lane == src) {
                        const u64 nh = pack16(mm, row, pc);
                        #pragma unroll
                        for (int j = 0; j < 8; j++) if (j == jd) h[j] = nh;
                    }
                }
            }
        }
    } else {
        // ---------- warps 0-6: streaming zero-fill, overlapped with the loop ----------
        float4* o4 = (float4*)obase;
        const float4 z4 = make_float4(0.f, 0.f, 0.f, 0.f);
        #pragma unroll 1
        for (int i = tid; i < NN * NN / 4; i += 224) __stcs(o4 + i, z4);
    }

    __syncthreads();   // zero STGs ordered before the ones; s_perm visible

    // ---------- one-hot: thread tid owns row tid ----------
    obase[(size_t)tid * NN + s_perm[tid]] = 1.0f;
}

extern "C" void kernel_launch(void* const* d_in, const int* in_sizes, int n_in,
                              void* d_out, int out_size) {
    const float* soft = (const float*)d_in[0];
    float* out = (float*)d_out;
    greedy_perm_kernel<<<256, 256>>>(soft, out);
}

// round 10
// speedup vs baseline: 1.3313x; 1.3313x over previous
#include <cuda_runtime.h>
#include <cstdint>

// B=256, N=256. Greedy masked argmax (exact reference semantics: max value,
// tie -> smallest flat index). Keys = fp32 bits; softmax values in (0,1) =>
// positive, < 1.0f => order-monotone uint32, < 2^30.
// Packed slot: u64 h = (key << 16) | (~((row<<8)|col) & 0xFFFF); u64 max ==
// lexicographic (max key, min flat index). 0 = dead.
//
// One CTA per batch, 256 threads:
//   init : all 8 warps, per-row argmax (coalesced float4, 2 REDUX/row) -> s_top
//          (also warms this SM's L1 with the whole score matrix for rescans)
//   loop : warp 7 (highest wid => SMSP arbiter priority) runs the serial
//          greedy loop — R6 winner body: u64 tree + 2 REDUX, single ballot,
//          eager cooperative rescans, static indexing everywhere.
//   warps 0-6: overlapped STREAMING (__stcs) zero-fill of the output.
//   epilogue : thread tid writes row tid's single 1.0.

#define NN 256
#define FULL 0xFFFFFFFFu
typedef unsigned long long u64;

__device__ __forceinline__ u64 pairmax(u64 a, u64 b) { return a > b ? a : b; }

__global__ __launch_bounds__(256)
void greedy_perm_kernel(const float* __restrict__ scores, float* __restrict__ out) {
    __shared__ u64 s_top[NN];   // packed head per row
    __shared__ int s_perm[NN];

    const int b    = blockIdx.x;
    const int tid  = threadIdx.x;
    const int warp = tid >> 5;
    const int lane = tid & 31;
    const float* base  = scores + (size_t)b * NN * NN;
    float*       obase = out    + (size_t)b * NN * NN;

    // ---------- parallel init: warp w -> rows w*32 .. w*32+31 ----------
    #pragma unroll 1
    for (int rg = 0; rg < 8; rg++) {
        const int row0 = warp * 32 + rg * 4;
        float4 A[4], Bq[4];
        #pragma unroll
        for (int q = 0; q < 4; q++) {
            const float4* rp = (const float4*)(base + (size_t)(row0 + q) * NN);
            A[q]  = __ldg(rp + lane);
            Bq[q] = __ldg(rp + 32 + lane);
        }
        #pragma unroll
        for (int q = 0; q < 4; q++) {
            const int row = row0 + q;
            const int c0 = 4 * lane;
            u64 w[8];
            w[0] = ((u64)__float_as_uint(A[q].x)  << 32) | (unsigned)~(c0 + 0);
            w[1] = ((u64)__float_as_uint(A[q].y)  << 32) | (unsigned)~(c0 + 1);
            w[2] = ((u64)__float_as_uint(A[q].z)  << 32) | (unsigned)~(c0 + 2);
            w[3] = ((u64)__float_as_uint(A[q].w)  << 32) | (unsigned)~(c0 + 3);
            w[4] = ((u64)__float_as_uint(Bq[q].x) << 32) | (unsigned)~(128 + c0 + 0);
            w[5] = ((u64)__float_as_uint(Bq[q].y) << 32) | (unsigned)~(128 + c0 + 1);
            w[6] = ((u64)__float_as_uint(Bq[q].z) << 32) | (unsigned)~(128 + c0 + 2);
            w[7] = ((u64)__float_as_uint(Bq[q].w) << 32) | (unsigned)~(128 + c0 + 3);
            u64 loc = pairmax(pairmax(pairmax(w[0], w[1]), pairmax(w[2], w[3])),
                              pairmax(pairmax(w[4], w[5]), pairmax(w[6], w[7])));
            const unsigned k1 = (unsigned)(loc >> 32);
            const unsigned c1 = (~(unsigned)loc) & 255u;
            const unsigned m1 = __reduce_max_sync(FULL, k1);
            const unsigned p1 = __reduce_min_sync(FULL, (k1 == m1) ? c1 : FULL);
            if (lane == 0)
                s_top[row] = ((u64)m1 << 16) |
                             (u64)((~(unsigned)((row << 8) | (int)p1)) & 0xFFFFu);
        }
    }
    __syncthreads();

    if (warp == 7) {
        // ---------- serial greedy loop (R6 winner body) ----------
        u64 h[8];
        unsigned cmask[8];
        #pragma unroll
        for (int k = 0; k < 8; k++) cmask[k] = 0u;
        #pragma unroll
        for (int j = 0; j < 8; j++) h[j] = s_top[j * 32 + lane];

        #pragma unroll 1
        for (int it = 0; it < NN; it++) {
            u64 loc = pairmax(pairmax(pairmax(h[0], h[1]), pairmax(h[2], h[3])),
                              pairmax(pairmax(h[4], h[5]), pairmax(h[6], h[7])));
            const unsigned bk = (unsigned)(loc >> 16);       // 30-bit key
            const unsigned cp = (~(unsigned)loc) & 0xFFFFu;  // (row<<8)|col

            const unsigned m   = __reduce_max_sync(FULL, bk);
            const unsigned sel = __reduce_min_sync(FULL, (bk == m) ? cp : FULL);
            const int r = (int)(sel >> 8);
            const int c = (int)(sel & 255u);

            if (lane == 0) s_perm[r] = c;

            // mask col c (replicated, static indexing)
            {
                const int w2 = c >> 5; const unsigned bit = 1u << (c & 31);
                #pragma unroll
                for (int k = 0; k < 8; k++) if (k == w2) cmask[k] |= bit;
            }
            // kill assigned row
            if (lane == (r & 31)) {
                const int slot = r >> 5;
                #pragma unroll
                for (int j = 0; j < 8; j++) if (j == slot) h[j] = 0ull;
            }

            if (it == NN - 1) break;

            // rows whose cached argmax col just got masked -> eager rescan
            unsigned need = 0u;
            #pragma unroll
            for (int j = 0; j < 8; j++)
                if ((unsigned)(h[j] >> 16) != 0u &&
                    (((~(unsigned)h[j]) & 255u) == (unsigned)c))
                    need |= (1u << j);

            unsigned ln = __ballot_sync(FULL, need != 0u);
            while (ln) {
                const int src = __ffs(ln) - 1; ln &= ln - 1;
                unsigned em = __shfl_sync(FULL, need, src);
                while (em) {
                    const int jd = __ffs(em) - 1; em &= em - 1;
                    const int row = jd * 32 + src;
                    const float* rp = base + (size_t)row * NN;
                    u64 w[8];
                    #pragma unroll
                    for (int k = 0; k < 8; k++) {
                        const float v = __ldg(rp + k * 32 + lane);
                        const unsigned key =
                            ((cmask[k] >> lane) & 1u) ? 0u : __float_as_uint(v);
                        w[k] = ((u64)key << 32) | (unsigned)~(unsigned)(k * 32 + lane);
                    }
                    u64 lq = pairmax(pairmax(pairmax(w[0], w[1]), pairmax(w[2], w[3])),
                                     pairmax(pairmax(w[4], w[5]), pairmax(w[6], w[7])));
                    const unsigned kk = (unsigned)(lq >> 32);
                    const unsigned cc = (~(unsigned)lq) & 255u;
                    const unsigned mm = __reduce_max_sync(FULL, kk);
                    const unsigned pc = __reduce_min_sync(FULL, (kk == mm) ? cc : FULL);
                    if (lane == src) {
                        const u64 nh = ((u64)mm << 16) |
                            (u64)((~(unsigned)((row << 8) | (int)pc)) & 0xFFFFu);
                        #pragma unroll
                        for (int j = 0; j < 8; j++) if (j == jd) h[j] = nh;
                    }
                }
            }
        }
    } else {
        // ---------- warps 0-6: streaming zero-fill, overlapped with the loop ----------
        float4* o4 = (float4*)obase;
        const float4 z4 = make_float4(0.f, 0.f, 0.f, 0.f);
        #pragma unroll 1
        for (int i = tid; i < NN * NN / 4; i += 224) __stcs(o4 + i, z4);
    }

    __syncthreads();   // zero STGs ordered before the ones; s_perm visible

    // ---------- one-hot: thread tid owns row tid ----------
    obase[(size_t)tid * NN + s_perm[tid]] = 1.0f;
}

extern "C" void kernel_launch(void* const* d_in, const int* in_sizes, int n_in,
                              void* d_out, int out_size) {
    const float* soft = (const float*)d_in[0];
    float* out = (float*)d_out;
    greedy_perm_kernel<<<256, 256>>>(soft, out);
}

// round 11
// speedup vs baseline: 1.6265x; 1.2217x over previous
#include <cuda_runtime.h>
#include <cstdint>

// B=256, N=256. Greedy masked argmax (exact reference semantics: max value,
// tie -> smallest flat index). Keys = fp32 bits; softmax values in (0,1) =>
// positive, < 1.0f => order-monotone uint32, < 2^30.
// Packed slot: u64 h = (key << 16) | (~((row<<8)|col) & 0xFFFF); u64 max ==
// lexicographic (max key, min flat index). 0 = dead.
//
// One CTA per batch, 256 threads:
//   init : all 8 warps, per-row argmax (coalesced float4, 2 REDUX/row) -> s_top
//          (warms this SM's L1 with the score matrix for the loop's rescans)
//   loop : warp 0 runs the serial greedy loop (R6 winner body: u64 tree +
//          2 REDUX, single ballot, eager cooperative rescans, static indexing).
//          Warps 1-7 SLEEP at the barrier — no contention during the loop.
//   epi  : all 8 warps do the fused zero+one-hot writeout (coalesced float4).

#define NN 256
#define FULL 0xFFFFFFFFu
typedef unsigned long long u64;

__device__ __forceinline__ u64 pairmax(u64 a, u64 b) { return a > b ? a : b; }

__global__ __launch_bounds__(256)
void greedy_perm_kernel(const float* __restrict__ scores, float* __restrict__ out) {
    __shared__ u64 s_top[NN];   // packed head per row
    __shared__ int s_perm[NN];

    const int b    = blockIdx.x;
    const int tid  = threadIdx.x;
    const int warp = tid >> 5;
    const int lane = tid & 31;
    const float* base  = scores + (size_t)b * NN * NN;
    float*       obase = out    + (size_t)b * NN * NN;

    // ---------- parallel init: warp w -> rows w*32 .. w*32+31 ----------
    #pragma unroll 1
    for (int rg = 0; rg < 8; rg++) {
        const int row0 = warp * 32 + rg * 4;
        float4 A[4], Bq[4];
        #pragma unroll
        for (int q = 0; q < 4; q++) {
            const float4* rp = (const float4*)(base + (size_t)(row0 + q) * NN);
            A[q]  = __ldg(rp + lane);
            Bq[q] = __ldg(rp + 32 + lane);
        }
        #pragma unroll
        for (int q = 0; q < 4; q++) {
            const int row = row0 + q;
            const int c0 = 4 * lane;
            u64 w[8];
            w[0] = ((u64)__float_as_uint(A[q].x)  << 32) | (unsigned)~(c0 + 0);
            w[1] = ((u64)__float_as_uint(A[q].y)  << 32) | (unsigned)~(c0 + 1);
            w[2] = ((u64)__float_as_uint(A[q].z)  << 32) | (unsigned)~(c0 + 2);
            w[3] = ((u64)__float_as_uint(A[q].w)  << 32) | (unsigned)~(c0 + 3);
            w[4] = ((u64)__float_as_uint(Bq[q].x) << 32) | (unsigned)~(128 + c0 + 0);
            w[5] = ((u64)__float_as_uint(Bq[q].y) << 32) | (unsigned)~(128 + c0 + 1);
            w[6] = ((u64)__float_as_uint(Bq[q].z) << 32) | (unsigned)~(128 + c0 + 2);
            w[7] = ((u64)__float_as_uint(Bq[q].w) << 32) | (unsigned)~(128 + c0 + 3);
            u64 loc = pairmax(pairmax(pairmax(w[0], w[1]), pairmax(w[2], w[3])),
                              pairmax(pairmax(w[4], w[5]), pairmax(w[6], w[7])));
            const unsigned k1 = (unsigned)(loc >> 32);
            const unsigned c1 = (~(unsigned)loc) & 255u;
            const unsigned m1 = __reduce_max_sync(FULL, k1);
            const unsigned p1 = __reduce_min_sync(FULL, (k1 == m1) ? c1 : FULL);
            if (lane == 0)
                s_top[row] = ((u64)m1 << 16) |
                             (u64)((~(unsigned)((row << 8) | (int)p1)) & 0xFFFFu);
        }
    }
    __syncthreads();

    if (warp == 0) {
        // ---------- serial greedy loop (R6 winner body) ----------
        u64 h[8];
        unsigned cmask[8];
        #pragma unroll
        for (int k = 0; k < 8; k++) cmask[k] = 0u;
        #pragma unroll
        for (int j = 0; j < 8; j++) h[j] = s_top[j * 32 + lane];

        #pragma unroll 1
        for (int it = 0; it < NN; it++) {
            u64 loc = pairmax(pairmax(pairmax(h[0], h[1]), pairmax(h[2], h[3])),
                              pairmax(pairmax(h[4], h[5]), pairmax(h[6], h[7])));
            const unsigned bk = (unsigned)(loc >> 16);       // 30-bit key
            const unsigned cp = (~(unsigned)loc) & 0xFFFFu;  // (row<<8)|col

            const unsigned m   = __reduce_max_sync(FULL, bk);
            const unsigned sel = __reduce_min_sync(FULL, (bk == m) ? cp : FULL);
            const int r = (int)(sel >> 8);
            const int c = (int)(sel & 255u);

            if (lane == 0) s_perm[r] = c;

            // mask col c (replicated, static indexing)
            {
                const int w2 = c >> 5; const unsigned bit = 1u << (c & 31);
                #pragma unroll
                for (int k = 0; k < 8; k++) if (k == w2) cmask[k] |= bit;
            }
            // kill assigned row
            if (lane == (r & 31)) {
                const int slot = r >> 5;
                #pragma unroll
                for (int j = 0; j < 8; j++) if (j == slot) h[j] = 0ull;
            }

            if (it == NN - 1) break;

            // rows whose cached argmax col just got masked -> eager rescan
            unsigned need = 0u;
            #pragma unroll
            for (int j = 0; j < 8; j++)
                if ((unsigned)(h[j] >> 16) != 0u &&
                    (((~(unsigned)h[j]) & 255u) == (unsigned)c))
                    need |= (1u << j);

            unsigned ln = __ballot_sync(FULL, need != 0u);
            while (ln) {
                const int src = __ffs(ln) - 1; ln &= ln - 1;
                unsigned em = __shfl_sync(FULL, need, src);
                while (em) {
                    const int jd = __ffs(em) - 1; em &= em - 1;
                    const int row = jd * 32 + src;
                    const float* rp = base + (size_t)row * NN;
                    u64 w[8];
                    #pragma unroll
                    for (int k = 0; k < 8; k++) {
                        const float v = __ldg(rp + k * 32 + lane);
                        const unsigned key =
                            ((cmask[k] >> lane) & 1u) ? 0u : __float_as_uint(v);
                        w[k] = ((u64)key << 32) | (unsigned)~(unsigned)(k * 32 + lane);
                    }
                    u64 lq = pairmax(pairmax(pairmax(w[0], w[1]), pairmax(w[2], w[3])),
                                     pairmax(pairmax(w[4], w[5]), pairmax(w[6], w[7])));
                    const unsigned kk = (unsigned)(lq >> 32);
                    const unsigned cc = (~(unsigned)lq) & 255u;
                    const unsigned mm = __reduce_max_sync(FULL, kk);
                    const unsigned pc = __reduce_min_sync(FULL, (kk == mm) ? cc : FULL);
                    if (lane == src) {
                        const u64 nh = ((u64)mm << 16) |
                            (u64)((~(unsigned)((row << 8) | (int)pc)) & 0xFFFFu);
                        #pragma unroll
                        for (int j = 0; j < 8; j++) if (j == jd) h[j] = nh;
                    }
                }
            }
        }
    }
    // warps 1-7 arrive immediately and sleep (deferred block) — no issue
    // pressure, no memory traffic during the serial loop.
    __syncthreads();

    // ---------- fused writeout: zeros + one-hot, 8 warps, coalesced float4 ----------
    #pragma unroll 1
    for (int rr = 0; rr < 32; rr++) {
        const int row = warp * 32 + rr;
        const int pc = s_perm[row];  // broadcast LDS
        float4* op = (float4*)(obase + (size_t)row * NN);
        #pragma unroll
        for (int hh = 0; hh < 2; hh++) {
            const int f4 = lane + 32 * hh;
            const int c0 = 4 * f4;
            float4 vv;
            vv.x = (pc == c0 + 0) ? 1.0f : 0.0f;
            vv.y = (pc == c0 + 1) ? 1.0f : 0.0f;
            vv.z = (pc == c0 + 2) ? 1.0f : 0.0f;
            vv.w = (pc == c0 + 3) ? 1.0f : 0.0f;
            op[f4] = vv;
        }
    }
}

extern "C" void kernel_launch(void* const* d_in, const int* in_sizes, int n_in,
                              void* d_out, int out_size) {
    const float* soft = (const float*)d_in[0];
    float* out = (float*)d_out;
    greedy_perm_kernel<<<256, 256>>>(soft, out);
}